// round 10
// baseline (speedup 1.0000x reference)
#include <cuda_runtime.h>
#include <cuda_bf16.h>
#include <cstdint>
#include <limits.h>

#define NPTS 4096
#define DIM  768
#define WD   64
#define KTOP 100

#define BM   128
#define NKT  (DIM / 16)     // 48 k-steps of 16
#define PADK 24             // smem row stride in bf16 (48B -> conflict-free LDSM)
#define TAU  0.05f          // |acc| below this -> exact fp32 sign repair (~250 sigma)
#define TBA  (BM * PADK * 2)        // bytes per tile array (6144)
#define SMEM_DYN (8 * TBA)          // 2 bufs x {Ah,Al,Bh,Bl} = 49152

// scratch (no allocations allowed)
__device__ int            g_counts[NPTS];
__device__ int            g_seed;
__device__ float          g_simseed[NPTS];
__device__ int            g_s[NPTS];
__device__ __nv_bfloat16  g_Xh[NPTS * DIM];     // bf16 hi part (6.3MB)
__device__ __nv_bfloat16  g_Xl[NPTS * DIM];     // bf16 lo part (6.3MB)

// ---------------------------------------------------------------------------
// helpers: ldmatrix + mma
// ---------------------------------------------------------------------------
__device__ __forceinline__ void ldsm_x4(uint32_t r[4], uint32_t addr) {
    asm volatile("ldmatrix.sync.aligned.m8n8.x4.shared.b16 {%0,%1,%2,%3}, [%4];"
                 : "=r"(r[0]), "=r"(r[1]), "=r"(r[2]), "=r"(r[3]) : "r"(addr));
}
__device__ __forceinline__ void mma_bf16(float d[4], const uint32_t a[4],
                                         uint32_t b0, uint32_t b1) {
    asm volatile("mma.sync.aligned.m16n8k16.row.col.f32.bf16.bf16.f32 "
                 "{%0,%1,%2,%3},{%4,%5,%6,%7},{%8,%9},{%0,%1,%2,%3};"
                 : "+f"(d[0]), "+f"(d[1]), "+f"(d[2]), "+f"(d[3])
                 : "r"(a[0]), "r"(a[1]), "r"(a[2]), "r"(a[3]), "r"(b0), "r"(b1));
}

__device__ __forceinline__ float exact_dot(const float* __restrict__ X, int gi, int gj) {
    const float4* a = (const float4*)(X + (size_t)gi * DIM);
    const float4* b = (const float4*)(X + (size_t)gj * DIM);
    float s = 0.0f;
    #pragma unroll 4
    for (int d = 0; d < DIM / 4; d++) {
        float4 u = a[d], w = b[d];
        s += u.x * w.x + u.y * w.y + u.z * w.z + u.w * w.w;
    }
    return s;
}

// ---------------------------------------------------------------------------
// 0) fp32 -> (bf16 hi, bf16 lo) split + counts init (fused)
// ---------------------------------------------------------------------------
__global__ void convert_split(const float* __restrict__ X) {
    int i = blockIdx.x * blockDim.x + threadIdx.x;   // one float4 per thread
    if (i < NPTS) g_counts[i] = 1;                   // diagonal always >= 0
    float4 v = ((const float4*)X)[i];
    __nv_bfloat16 hx = __float2bfloat16_rn(v.x);
    __nv_bfloat16 hy = __float2bfloat16_rn(v.y);
    __nv_bfloat16 hz = __float2bfloat16_rn(v.z);
    __nv_bfloat16 hw = __float2bfloat16_rn(v.w);
    float lx = v.x - __bfloat162float(hx);
    float ly = v.y - __bfloat162float(hy);
    float lz = v.z - __bfloat162float(hz);
    float lw = v.w - __bfloat162float(hw);
    __nv_bfloat162* oh = (__nv_bfloat162*)g_Xh;
    __nv_bfloat162* ol = (__nv_bfloat162*)g_Xl;
    oh[2 * i + 0] = __nv_bfloat162(hx, hy);
    oh[2 * i + 1] = __nv_bfloat162(hz, hw);
    ol[2 * i + 0] = __floats2bfloat162_rn(lx, ly);
    ol[2 * i + 1] = __floats2bfloat162_rn(lz, lw);
}

// ---------------------------------------------------------------------------
// 1) triangular count-GEMM, 3-pass bf16 HMMA (hh+hl+lh), double-buffered
//    dynamic smem, ONE sync per k-step, register prefetch. 528 linear tiles.
// ---------------------------------------------------------------------------
__global__ __launch_bounds__(256)
void count_mma(const float* __restrict__ X) {
    // decode triangular tile index: row bi starts at C(bi) = bi*(65-bi)/2
    int t = blockIdx.x;
    int bi = (int)((65.0 - sqrt(4225.0 - 8.0 * (double)t)) * 0.5);
    while (bi * (65 - bi) / 2 > t) bi--;
    while ((bi + 1) * (64 - bi) / 2 <= t) bi++;
    int bj = bi + (t - bi * (65 - bi) / 2);

    extern __shared__ __nv_bfloat16 dynsm[];   // [buf(2)][arr(4)][BM*PADK]
    __shared__ int rowSum[BM];
    __shared__ int colSum[BM];

    int tid  = threadIdx.x;
    int warp = tid >> 5, lane = tid & 31;
    int wm = warp & 3;          // M group: rows wm*32..+31
    int wn = warp >> 2;         // N group: cols wn*64..+63
    int i0 = bi * BM, j0 = bj * BM;

    float acc[2][8][4];
    #pragma unroll
    for (int im = 0; im < 2; im++)
        #pragma unroll
        for (int jn = 0; jn < 8; jn++)
            #pragma unroll
            for (int e = 0; e < 4; e++) acc[im][jn][e] = 0.0f;

    // global load mapping: thread -> (row, 16B half) of the 128x16 stage
    int lrow = tid >> 1, lhalf = tid & 1;
    const uint4* gah = (const uint4*)(g_Xh + (size_t)(i0 + lrow) * DIM);
    const uint4* gal = (const uint4*)(g_Xl + (size_t)(i0 + lrow) * DIM);
    const uint4* gbh = (const uint4*)(g_Xh + (size_t)(j0 + lrow) * DIM);
    const uint4* gbl = (const uint4*)(g_Xl + (size_t)(j0 + lrow) * DIM);
    uint32_t stoff = (uint32_t)((lrow * PADK + lhalf * 8) * 2);   // byte offset in array
    char* smbase = (char*)dynsm;

    // ldmatrix source lanes
    int rowA  = lane & 15;
    int koffA = (lane >> 4) * 8;
    int grp   = lane >> 3;
    int nB    = ((grp >> 1) * 8) + (lane & 7);
    int koffB = (grp & 1) * 8;

    uint32_t smadr = (uint32_t)__cvta_generic_to_shared(dynsm);
    uint32_t aAddrH[2], aAddrL[2], bAddrH[4], bAddrL[4];
    #pragma unroll
    for (int im = 0; im < 2; im++) {
        uint32_t off = ((wm * 32 + im * 16 + rowA) * PADK + koffA) * 2;
        aAddrH[im] = smadr + off;            // arr 0 (Ah)
        aAddrL[im] = smadr + TBA + off;      // arr 1 (Al)
    }
    #pragma unroll
    for (int jb = 0; jb < 4; jb++) {
        uint32_t off = ((wn * 64 + jb * 16 + nB) * PADK + koffB) * 2;
        bAddrH[jb] = smadr + 2 * TBA + off;  // arr 2 (Bh)
        bAddrL[jb] = smadr + 3 * TBA + off;  // arr 3 (Bl)
    }
    const uint32_t bufBytes = 4 * TBA;

    uint4 rah, ral, rbh, rbl;
    rah = gah[lhalf]; ral = gal[lhalf]; rbh = gbh[lhalf]; rbl = gbl[lhalf];
    *(uint4*)(smbase          + stoff) = rah;
    *(uint4*)(smbase + TBA    + stoff) = ral;
    *(uint4*)(smbase + 2*TBA  + stoff) = rbh;
    *(uint4*)(smbase + 3*TBA  + stoff) = rbl;
    __syncthreads();

    for (int kt = 0; kt < NKT; kt++) {
        int b = kt & 1;
        if (kt + 1 < NKT) {          // prefetch next stage into registers
            int o = (kt + 1) * 2 + lhalf;
            rah = gah[o]; ral = gal[o]; rbh = gbh[o]; rbl = gbl[o];
        }

        uint32_t ah[2][4], al[2][4], bh[4][4], bl[4][4];
        uint32_t bo = b * bufBytes;
        #pragma unroll
        for (int im = 0; im < 2; im++) {
            ldsm_x4(ah[im], aAddrH[im] + bo);
            ldsm_x4(al[im], aAddrL[im] + bo);
        }
        #pragma unroll
        for (int jb = 0; jb < 4; jb++) {
            ldsm_x4(bh[jb], bAddrH[jb] + bo);
            ldsm_x4(bl[jb], bAddrL[jb] + bo);
        }

        if (kt + 1 < NKT) {          // stores to the OTHER buffer (safe: synced at kt-1)
            char* dst = smbase + (b ^ 1) * bufBytes;
            *(uint4*)(dst          + stoff) = rah;
            *(uint4*)(dst + TBA    + stoff) = ral;
            *(uint4*)(dst + 2*TBA  + stoff) = rbh;
            *(uint4*)(dst + 3*TBA  + stoff) = rbl;
        }

        #pragma unroll
        for (int im = 0; im < 2; im++)
            #pragma unroll
            for (int jn = 0; jn < 8; jn++) {
                int jb = jn >> 1, o = (jn & 1) * 2;
                mma_bf16(acc[im][jn], ah[im], bh[jb][o], bh[jb][o + 1]);
                mma_bf16(acc[im][jn], ah[im], bl[jb][o], bl[jb][o + 1]);
                mma_bf16(acc[im][jn], al[im], bh[jb][o], bh[jb][o + 1]);
            }

        __syncthreads();             // one sync per k-step
    }

    // ---- epilogue: signs (+ rare exact repair), row/col counts ----
    if (tid < BM) { rowSum[tid] = 0; colSum[tid] = 0; }
    __syncthreads();

    bool diag = (bi == bj);
    int rcnt[2][2];  rcnt[0][0] = rcnt[0][1] = rcnt[1][0] = rcnt[1][1] = 0;
    int ccnt[16];
    #pragma unroll
    for (int q = 0; q < 16; q++) ccnt[q] = 0;

    int rbase = wm * 32 + (lane >> 2);
    int cbase = wn * 64 + (lane & 3) * 2;

    #pragma unroll
    for (int im = 0; im < 2; im++) {
        #pragma unroll
        for (int jn = 0; jn < 8; jn++) {
            #pragma unroll
            for (int e4 = 0; e4 < 4; e4++) {
                int h = e4 >> 1, e = e4 & 1;
                int gi = i0 + rbase + im * 16 + h * 8;
                int gj = j0 + cbase + jn * 8 + e;
                if (diag && gj <= gi) continue;
                float v = acc[im][jn][e4];
                int c;
                if (fabsf(v) >= TAU) c = (v >= 0.0f);
                else                 c = (exact_dot(X, gi, gj) >= 0.0f);
                rcnt[im][h] += c;
                ccnt[jn * 2 + e] += c;
            }
        }
    }
    #pragma unroll
    for (int im = 0; im < 2; im++)
        #pragma unroll
        for (int h = 0; h < 2; h++)
            atomicAdd(&rowSum[rbase + im * 16 + h * 8], rcnt[im][h]);
    #pragma unroll
    for (int jn = 0; jn < 8; jn++)
        #pragma unroll
        for (int e = 0; e < 2; e++)
            atomicAdd(&colSum[cbase + jn * 8 + e], ccnt[jn * 2 + e]);
    __syncthreads();

    if (tid < BM) {
        if (rowSum[tid]) atomicAdd(&g_counts[i0 + tid], rowSum[tid]);
        if (colSum[tid]) atomicAdd(&g_counts[j0 + tid], colSum[tid]);
    }
}

// ---------------------------------------------------------------------------
// 2) argmin of counts (first occurrence) + seed blend w/ round-half-to-even
// ---------------------------------------------------------------------------
__global__ void seed_kernel(const int* __restrict__ attn_seed) {
    __shared__ int bestC[256], bestI[256];
    int tid = threadIdx.x;
    int bc = INT_MAX, bi = 0;
    for (int i = tid; i < NPTS; i += 256) {
        int c = g_counts[i];
        if (c < bc) { bc = c; bi = i; }
    }
    bestC[tid] = bc; bestI[tid] = bi;
    __syncthreads();
    for (int s = 128; s > 0; s >>= 1) {
        if (tid < s) {
            if (bestC[tid + s] < bestC[tid] ||
                (bestC[tid + s] == bestC[tid] && bestI[tid + s] < bestI[tid])) {
                bestC[tid] = bestC[tid + s];
                bestI[tid] = bestI[tid + s];
            }
        }
        __syncthreads();
    }
    if (tid == 0) {
        int idx = bestI[0];
        int r = idx / WD, c = idx % WD;
        int tr = r + attn_seed[0];
        int tc = c + attn_seed[1];
        int rr = tr >> 1; if (tr & 1) rr += (rr & 1);   // round half-to-even
        int cc = tc >> 1; if (tc & 1) cc += (cc & 1);
        g_seed = rr * WD + cc;
    }
}

// ---------------------------------------------------------------------------
// 3) sim[seed][j] for all j + initial mask s[j] = (sim >= 0). warp per j.
// ---------------------------------------------------------------------------
__global__ void seedrow_kernel(const float* __restrict__ X) {
    int gwarp = (blockIdx.x * blockDim.x + threadIdx.x) >> 5;
    int lane  = threadIdx.x & 31;
    if (gwarp >= NPTS) return;
    int seed = g_seed;
    const float* xs = X + (size_t)seed * DIM;
    const float* xj = X + (size_t)gwarp * DIM;
    float p = 0.0f;
    for (int d = lane; d < DIM; d += 32) p += xs[d] * xj[d];
    #pragma unroll
    for (int o = 16; o > 0; o >>= 1) p += __shfl_down_sync(0xffffffffu, p, o);
    if (lane == 0) {
        g_simseed[gwarp] = p;
        g_s[gwarp] = (p >= 0.0f) ? 1 : 0;
    }
}

// ---------------------------------------------------------------------------
// 4) bitonic sort (desc value, asc index tiebreak) -> keep top-100, mask s
// ---------------------------------------------------------------------------
__global__ void topk_kernel() {
    __shared__ float sv[NPTS];
    __shared__ int   si[NPTS];
    int tid = threadIdx.x;   // 1024 threads
    int seed = g_seed;
    for (int i = tid; i < NPTS; i += 1024) { sv[i] = g_simseed[i]; si[i] = i; }
    __syncthreads();
    for (int k = 2; k <= NPTS; k <<= 1) {
        for (int j = k >> 1; j > 0; j >>= 1) {
            for (int i = tid; i < NPTS; i += 1024) {
                int ixj = i ^ j;
                if (ixj > i) {
                    float v1 = sv[i], v2 = sv[ixj];
                    int a = si[i], b = si[ixj];
                    bool g = (v1 < v2) || (v1 == v2 && a > b);
                    bool dirAsc = ((i & k) == 0);
                    if (g == dirAsc) { sv[i] = v2; sv[ixj] = v1; si[i] = b; si[ixj] = a; }
                }
            }
            __syncthreads();
        }
    }
    float v99 = sv[KTOP - 1];
    int   i99 = si[KTOP - 1];
    for (int i = tid; i < NPTS; i += 1024) {
        int s = g_s[i];
        if (i == seed) s = 1;
        float v = g_simseed[i];
        bool keep = (v > v99) || (v == v99 && i <= i99);
        g_s[i] = keep ? s : 0;
    }
}

// ---------------------------------------------------------------------------
// 5) sequential expansion, single warp, register-resident accumulator.
// ---------------------------------------------------------------------------
__global__ void scan_kernel(const float* __restrict__ X) {
    __shared__ int list[KTOP + 32];
    int lane = threadIdx.x;   // 32 threads

    int cnt = 0;
    for (int c = 0; c < NPTS / 32; c++) {
        int idx = c * 32 + lane;
        int val = g_s[idx];
        unsigned m = __ballot_sync(0xffffffffu, val != 0);
        if (val) {
            int pos = cnt + __popc(m & ((1u << lane) - 1));
            if (pos < KTOP + 32) list[pos] = idx;
        }
        cnt += __popc(m);
    }
    int na = (cnt < KTOP + 32) ? cnt : (KTOP + 32);
    __syncwarp();

    float v[DIM / 32];
    #pragma unroll
    for (int q = 0; q < DIM / 32; q++) v[q] = 0.0f;
    for (int l = 0; l < na; l++) {
        const float* x = X + (size_t)list[l] * DIM;
        #pragma unroll
        for (int q = 0; q < DIM / 32; q++) v[q] += x[lane + 32 * q];
    }

    for (int l = 0; l < na; l++) {
        int i = list[l];
        const float* x = X + (size_t)i * DIM;
        float xr[DIM / 32];
        float dot = 0.0f;
        #pragma unroll
        for (int q = 0; q < DIM / 32; q++) {
            xr[q] = x[lane + 32 * q];
            dot += xr[q] * v[q];
        }
        #pragma unroll
        for (int o = 16; o > 0; o >>= 1) dot += __shfl_xor_sync(0xffffffffu, dot, o);
        if (dot <= 0.0f) {
            if (lane == 0) g_s[i] = 0;
            #pragma unroll
            for (int q = 0; q < DIM / 32; q++) v[q] -= xr[q];
        }
    }
}

// ---------------------------------------------------------------------------
// 6) 8-connected components: in-place min-label propagation to fixpoint.
// ---------------------------------------------------------------------------
__global__ void cc_kernel(float* __restrict__ outp) {
    __shared__ int lab[66 * 66];
    __shared__ int changed;
    const int BIG = NPTS + 1;
    int tid = threadIdx.x;   // 1024 threads

    for (int p = tid; p < 66 * 66; p += 1024) lab[p] = BIG;
    __syncthreads();

    int fgp[4], pos[4];
    #pragma unroll
    for (int q = 0; q < 4; q++) {
        int p = tid + q * 1024;
        int r = p >> 6, c = p & 63;
        pos[q] = (r + 1) * 66 + (c + 1);
        fgp[q] = g_s[p];
        lab[pos[q]] = fgp[q] ? (p + 1) : BIG;
    }
    __syncthreads();

    while (true) {
        if (tid == 0) changed = 0;
        __syncthreads();
        int lc = 0;
        #pragma unroll
        for (int q = 0; q < 4; q++) {
            if (fgp[q]) {
                int pp = pos[q];
                int m = lab[pp];
                m = min(m, lab[pp - 67]); m = min(m, lab[pp - 66]); m = min(m, lab[pp - 65]);
                m = min(m, lab[pp - 1]);                            m = min(m, lab[pp + 1]);
                m = min(m, lab[pp + 65]); m = min(m, lab[pp + 66]); m = min(m, lab[pp + 67]);
                if (m < lab[pp]) { lab[pp] = m; lc = 1; }
            }
        }
        if (lc) changed = 1;
        __syncthreads();
        int done = !changed;
        __syncthreads();
        if (done) break;
    }

    #pragma unroll
    for (int q = 0; q < 4; q++) {
        int p = tid + q * 1024;
        outp[p] = fgp[q] ? (float)lab[pos[q]] : 0.0f;
    }
}

// ---------------------------------------------------------------------------
extern "C" void kernel_launch(void* const* d_in, const int* in_sizes, int n_in,
                              void* d_out, int out_size) {
    const float* X;
    const int*   attn;
    if (n_in >= 2 && in_sizes[0] == 2) {
        attn = (const int*)d_in[0];
        X    = (const float*)d_in[1];
    } else {
        X    = (const float*)d_in[0];
        attn = (const int*)d_in[1];
    }
    float* outp = (float*)d_out;

    cudaFuncSetAttribute(count_mma, cudaFuncAttributeMaxDynamicSharedMemorySize, SMEM_DYN);

    convert_split<<<(NPTS * DIM / 4) / 256, 256>>>(X);
    count_mma<<<528, 256, SMEM_DYN>>>(X);
    seed_kernel<<<1, 256>>>(attn);
    seedrow_kernel<<<NPTS / 8, 256>>>(X);
    topk_kernel<<<1, 1024>>>();
    scan_kernel<<<1, 32>>>(X);
    cc_kernel<<<1, 1024>>>(outp);
}

// round 11
// speedup vs baseline: 1.1179x; 1.1179x over previous
#include <cuda_runtime.h>
#include <cstdint>
#include <limits.h>

#define NPTS 4096
#define DIM  768
#define WD   64
#define KTOP 100

#define BM 128
#define BK 16
#define NKT (DIM / BK)   // 48

// scratch (no allocations allowed)
__device__ int   g_counts[NPTS];
__device__ int   g_best;            // packed argmin key: count*4096 + idx
__device__ float g_simseed[NPTS];
__device__ int   g_s[NPTS];

// ---------------------------------------------------------------------------
// seed blend from packed argmin key (round-half-to-even), exact integer math
// ---------------------------------------------------------------------------
__device__ __forceinline__ int blend_seed(int key, const int* __restrict__ attn) {
    int idx = key & 4095;
    int r = idx >> 6, c = idx & 63;
    int tr = r + attn[0];
    int tc = c + attn[1];
    int rr = tr >> 1; if (tr & 1) rr += (rr & 1);
    int cc = tc >> 1; if (tc & 1) cc += (cc & 1);
    return rr * WD + cc;
}

// ---------------------------------------------------------------------------
// 0) init: counts = 1 (diagonal always >= 0), g_best = INT_MAX
// ---------------------------------------------------------------------------
__global__ void init_kernel() {
    int i = blockIdx.x * blockDim.x + threadIdx.x;
    if (i < NPTS) g_counts[i] = 1;
    if (i == 0) g_best = INT_MAX;
}

// ---------------------------------------------------------------------------
// 1) triangular count-GEMM, exact fp32 via packed FFMA2 (fma.rn.f32x2).
//    128x128 tile, 16x16 threads, per-thread 8x8 as 4x8 f32x2 pairs over M.
//    Double-buffered smem, register prefetch, 528 linear triangular tiles.
// ---------------------------------------------------------------------------
__global__ __launch_bounds__(256, 2)
void count_ffma2(const float* __restrict__ X) {
    // decode triangular tile index t -> (bi, bj), bj >= bi
    int t = blockIdx.x;
    int bi = (int)((65.0 - sqrt(4225.0 - 8.0 * (double)t)) * 0.5);
    while (bi * (65 - bi) / 2 > t) bi--;
    while ((bi + 1) * (64 - bi) / 2 <= t) bi++;
    int bj = bi + (t - bi * (65 - bi) / 2);

    __shared__ __align__(16) float As[2][BK][BM + 4];
    __shared__ __align__(16) float Bs[2][BK][BM + 4];
    __shared__ int rowSum[BM];
    __shared__ int colSum[BM];

    int tid = threadIdx.x;
    int tx = tid & 15, ty = tid >> 4;
    int i0 = bi * BM, j0 = bj * BM;

    int lrow = tid >> 1;          // 0..127
    int lq4  = (tid & 1) * 8;     // 8 consecutive floats per thread

    // acc pairs over M: acc2[p][n] = {(ty*8+2p, tx*8+n), (ty*8+2p+1, tx*8+n)}
    unsigned long long acc2[4][8];
    #pragma unroll
    for (int p = 0; p < 4; p++)
        #pragma unroll
        for (int n = 0; n < 8; n++) acc2[p][n] = 0ull;

    float4 ra0, ra1, rb0, rb1;
    const float* abase = X + (size_t)(i0 + lrow) * DIM + lq4;
    const float* bbase = X + (size_t)(j0 + lrow) * DIM + lq4;

#define LDG_TILE(kt) {                                         \
        const float* ap = abase + (kt) * BK;                   \
        const float* bp = bbase + (kt) * BK;                   \
        ra0 = *(const float4*)(ap);  ra1 = *(const float4*)(ap + 4); \
        rb0 = *(const float4*)(bp);  rb1 = *(const float4*)(bp + 4); }

#define STS_TILE(buf) {                                        \
        As[buf][lq4+0][lrow]=ra0.x; As[buf][lq4+1][lrow]=ra0.y; \
        As[buf][lq4+2][lrow]=ra0.z; As[buf][lq4+3][lrow]=ra0.w; \
        As[buf][lq4+4][lrow]=ra1.x; As[buf][lq4+5][lrow]=ra1.y; \
        As[buf][lq4+6][lrow]=ra1.z; As[buf][lq4+7][lrow]=ra1.w; \
        Bs[buf][lq4+0][lrow]=rb0.x; Bs[buf][lq4+1][lrow]=rb0.y; \
        Bs[buf][lq4+2][lrow]=rb0.z; Bs[buf][lq4+3][lrow]=rb0.w; \
        Bs[buf][lq4+4][lrow]=rb1.x; Bs[buf][lq4+5][lrow]=rb1.y; \
        Bs[buf][lq4+6][lrow]=rb1.z; Bs[buf][lq4+7][lrow]=rb1.w; }

    LDG_TILE(0);
    STS_TILE(0);
    __syncthreads();

    for (int kt = 0; kt < NKT; kt++) {
        int buf = kt & 1;
        if (kt + 1 < NKT) LDG_TILE(kt + 1);

        #pragma unroll
        for (int k = 0; k < BK; k++) {
            // a: 8 consecutive rows -> 4 packed f32x2 (no movs)
            const ulonglong2* ap = (const ulonglong2*)&As[buf][k][ty * 8];
            ulonglong2 a01 = ap[0], a23 = ap[1];
            unsigned long long av[4];
            av[0] = a01.x; av[1] = a01.y; av[2] = a23.x; av[3] = a23.y;
            // b: 8 consecutive cols, duplicate each into a f32x2
            const float4* bp = (const float4*)&Bs[buf][k][tx * 8];
            float4 b0 = bp[0], b1 = bp[1];
            float bf[8] = {b0.x, b0.y, b0.z, b0.w, b1.x, b1.y, b1.z, b1.w};
            unsigned long long b2[8];
            #pragma unroll
            for (int n = 0; n < 8; n++)
                asm("mov.b64 %0, {%1, %2};" : "=l"(b2[n]) : "f"(bf[n]), "f"(bf[n]));
            #pragma unroll
            for (int p = 0; p < 4; p++)
                #pragma unroll
                for (int n = 0; n < 8; n++)
                    asm("fma.rn.f32x2 %0, %1, %2, %0;"
                        : "+l"(acc2[p][n]) : "l"(av[p]), "l"(b2[n]));
        }

        if (kt + 1 < NKT) STS_TILE(buf ^ 1);
        __syncthreads();
    }
#undef LDG_TILE
#undef STS_TILE

    // ---- epilogue: count nonnegatives per row and per column ----
    if (tid < BM) { rowSum[tid] = 0; colSum[tid] = 0; }
    __syncthreads();

    bool diag = (bi == bj);
    int rcnt[8], ccnt[8];
    #pragma unroll
    for (int m = 0; m < 8; m++) { rcnt[m] = 0; ccnt[m] = 0; }

    #pragma unroll
    for (int p = 0; p < 4; p++) {
        #pragma unroll
        for (int n = 0; n < 8; n++) {
            unsigned long long a = acc2[p][n];
            float vlo = __uint_as_float((unsigned)(a & 0xffffffffull));
            float vhi = __uint_as_float((unsigned)(a >> 32));
            int gj = j0 + tx * 8 + n;
            int gilo = i0 + ty * 8 + 2 * p;
            int clo = (vlo >= 0.0f) && (!diag || gj > gilo);
            int chi = (vhi >= 0.0f) && (!diag || gj > gilo + 1);
            rcnt[2 * p]     += clo;
            rcnt[2 * p + 1] += chi;
            ccnt[n] += clo + chi;
        }
    }
    #pragma unroll
    for (int m = 0; m < 8; m++) atomicAdd(&rowSum[ty * 8 + m], rcnt[m]);
    #pragma unroll
    for (int n = 0; n < 8; n++) atomicAdd(&colSum[tx * 8 + n], ccnt[n]);
    __syncthreads();

    if (tid < BM) {
        if (rowSum[tid]) atomicAdd(&g_counts[i0 + tid], rowSum[tid]);
        if (colSum[tid]) atomicAdd(&g_counts[j0 + tid], colSum[tid]);
    }
}

// ---------------------------------------------------------------------------
// 2) grid-wide argmin of counts via packed key atomicMin (first occurrence)
// ---------------------------------------------------------------------------
__global__ void argmin_kernel() {
    int i = blockIdx.x * blockDim.x + threadIdx.x;   // 4096 threads
    int key = g_counts[i] * 4096 + i;
    #pragma unroll
    for (int o = 16; o > 0; o >>= 1)
        key = min(key, __shfl_xor_sync(0xffffffffu, key, o));
    if ((threadIdx.x & 31) == 0) atomicMin(&g_best, key);
}

// ---------------------------------------------------------------------------
// 3) sim[seed][j] for all j + initial mask. warp per j, float4 loads.
// ---------------------------------------------------------------------------
__global__ void seedrow_kernel(const float* __restrict__ X,
                               const int* __restrict__ attn) {
    int gwarp = (blockIdx.x * blockDim.x + threadIdx.x) >> 5;
    int lane  = threadIdx.x & 31;
    if (gwarp >= NPTS) return;
    int seed = blend_seed(g_best, attn);
    const float4* xs = (const float4*)(X + (size_t)seed * DIM);
    const float4* xj = (const float4*)(X + (size_t)gwarp * DIM);
    float p = 0.0f;
    #pragma unroll
    for (int q = 0; q < 6; q++) {
        float4 u = xs[lane + 32 * q], w = xj[lane + 32 * q];
        p += u.x * w.x + u.y * w.y + u.z * w.z + u.w * w.w;
    }
    #pragma unroll
    for (int o = 16; o > 0; o >>= 1) p += __shfl_down_sync(0xffffffffu, p, o);
    if (lane == 0) {
        g_simseed[gwarp] = p;
        g_s[gwarp] = (p >= 0.0f) ? 1 : 0;
    }
}

// ---------------------------------------------------------------------------
// 4) bitonic sort (desc value, asc index tiebreak) -> keep top-100, mask s
// ---------------------------------------------------------------------------
__global__ void topk_kernel(const int* __restrict__ attn) {
    __shared__ float sv[NPTS];
    __shared__ int   si[NPTS];
    int tid = threadIdx.x;   // 1024 threads
    int seed = blend_seed(g_best, attn);
    for (int i = tid; i < NPTS; i += 1024) { sv[i] = g_simseed[i]; si[i] = i; }
    __syncthreads();
    for (int k = 2; k <= NPTS; k <<= 1) {
        for (int j = k >> 1; j > 0; j >>= 1) {
            for (int i = tid; i < NPTS; i += 1024) {
                int ixj = i ^ j;
                if (ixj > i) {
                    float v1 = sv[i], v2 = sv[ixj];
                    int a = si[i], b = si[ixj];
                    bool g = (v1 < v2) || (v1 == v2 && a > b);
                    bool dirAsc = ((i & k) == 0);
                    if (g == dirAsc) { sv[i] = v2; sv[ixj] = v1; si[i] = b; si[ixj] = a; }
                }
            }
            __syncthreads();
        }
    }
    float v99 = sv[KTOP - 1];
    int   i99 = si[KTOP - 1];
    for (int i = tid; i < NPTS; i += 1024) {
        int s = g_s[i];
        if (i == seed) s = 1;
        float v = g_simseed[i];
        bool keep = (v > v99) || (v == v99 && i <= i99);
        g_s[i] = keep ? s : 0;
    }
}

// ---------------------------------------------------------------------------
// 5) sequential expansion, single warp, float4 loads, register accumulator.
// ---------------------------------------------------------------------------
__global__ void scan_kernel(const float* __restrict__ X) {
    __shared__ int list[KTOP + 32];
    int lane = threadIdx.x;   // 32 threads

    int cnt = 0;
    for (int c = 0; c < NPTS / 32; c++) {
        int idx = c * 32 + lane;
        int val = g_s[idx];
        unsigned m = __ballot_sync(0xffffffffu, val != 0);
        if (val) {
            int pos = cnt + __popc(m & ((1u << lane) - 1));
            if (pos < KTOP + 32) list[pos] = idx;
        }
        cnt += __popc(m);
    }
    int na = (cnt < KTOP + 32) ? cnt : (KTOP + 32);
    __syncwarp();

    // v in registers as 6 float4 per lane (dims 4*(lane+32q)..+3)
    float4 v4[6];
    #pragma unroll
    for (int q = 0; q < 6; q++) v4[q] = make_float4(0.f, 0.f, 0.f, 0.f);
    for (int l = 0; l < na; l++) {
        const float4* x = (const float4*)(X + (size_t)list[l] * DIM);
        #pragma unroll
        for (int q = 0; q < 6; q++) {
            float4 u = x[lane + 32 * q];
            v4[q].x += u.x; v4[q].y += u.y; v4[q].z += u.z; v4[q].w += u.w;
        }
    }

    for (int l = 0; l < na; l++) {
        int i = list[l];
        const float4* x = (const float4*)(X + (size_t)i * DIM);
        float4 xr[6];
        float dot = 0.0f;
        #pragma unroll
        for (int q = 0; q < 6; q++) {
            xr[q] = x[lane + 32 * q];
            dot += xr[q].x * v4[q].x + xr[q].y * v4[q].y
                 + xr[q].z * v4[q].z + xr[q].w * v4[q].w;
        }
        #pragma unroll
        for (int o = 16; o > 0; o >>= 1) dot += __shfl_xor_sync(0xffffffffu, dot, o);
        if (dot <= 0.0f) {                 // grows = (sum > 0) fails -> drop
            if (lane == 0) g_s[i] = 0;
            #pragma unroll
            for (int q = 0; q < 6; q++) {
                v4[q].x -= xr[q].x; v4[q].y -= xr[q].y;
                v4[q].z -= xr[q].z; v4[q].w -= xr[q].w;
            }
        }
    }
}

// ---------------------------------------------------------------------------
// 6) 8-connected components: in-place min-label propagation to fixpoint.
// ---------------------------------------------------------------------------
__global__ void cc_kernel(float* __restrict__ outp) {
    __shared__ int lab[66 * 66];
    __shared__ int changed;
    const int BIG = NPTS + 1;
    int tid = threadIdx.x;   // 1024 threads

    for (int p = tid; p < 66 * 66; p += 1024) lab[p] = BIG;
    __syncthreads();

    int fgp[4], pos[4];
    #pragma unroll
    for (int q = 0; q < 4; q++) {
        int p = tid + q * 1024;
        int r = p >> 6, c = p & 63;
        pos[q] = (r + 1) * 66 + (c + 1);
        fgp[q] = g_s[p];
        lab[pos[q]] = fgp[q] ? (p + 1) : BIG;
    }
    __syncthreads();

    while (true) {
        if (tid == 0) changed = 0;
        __syncthreads();
        int lc = 0;
        #pragma unroll
        for (int q = 0; q < 4; q++) {
            if (fgp[q]) {
                int pp = pos[q];
                int m = lab[pp];
                m = min(m, lab[pp - 67]); m = min(m, lab[pp - 66]); m = min(m, lab[pp - 65]);
                m = min(m, lab[pp - 1]);                            m = min(m, lab[pp + 1]);
                m = min(m, lab[pp + 65]); m = min(m, lab[pp + 66]); m = min(m, lab[pp + 67]);
                if (m < lab[pp]) { lab[pp] = m; lc = 1; }
            }
        }
        if (lc) changed = 1;
        __syncthreads();
        int done = !changed;
        __syncthreads();
        if (done) break;
    }

    #pragma unroll
    for (int q = 0; q < 4; q++) {
        int p = tid + q * 1024;
        outp[p] = fgp[q] ? (float)lab[pos[q]] : 0.0f;
    }
}

// ---------------------------------------------------------------------------
extern "C" void kernel_launch(void* const* d_in, const int* in_sizes, int n_in,
                              void* d_out, int out_size) {
    const float* X;
    const int*   attn;
    if (n_in >= 2 && in_sizes[0] == 2) {
        attn = (const int*)d_in[0];
        X    = (const float*)d_in[1];
    } else {
        X    = (const float*)d_in[0];
        attn = (const int*)d_in[1];
    }
    float* outp = (float*)d_out;

    init_kernel<<<16, 256>>>();
    count_ffma2<<<528, 256>>>(X);
    argmin_kernel<<<16, 256>>>();
    seedrow_kernel<<<NPTS / 8, 256>>>(X, attn);
    topk_kernel<<<1, 1024>>>(attn);
    scan_kernel<<<1, 32>>>(X);
    cc_kernel<<<1, 1024>>>(outp);
}

// round 12
// speedup vs baseline: 1.1183x; 1.0004x over previous
#include <cuda_runtime.h>
#include <cstdint>
#include <limits.h>

#define NPTS 4096
#define DIM  768
#define WD   64
#define KTOP 100

#define BM 128
#define BK 16
#define NKT (DIM / BK)   // 48

// scratch (no allocations allowed)
__device__ int   g_counts[NPTS];
__device__ int   g_best;            // packed argmin key: count*4096 + idx
__device__ float g_simseed[NPTS];
__device__ int   g_s[NPTS];

// ---------------------------------------------------------------------------
// seed blend from packed argmin key (round-half-to-even), exact integer math
// ---------------------------------------------------------------------------
__device__ __forceinline__ int blend_seed(int key, const int* __restrict__ attn) {
    int idx = key & 4095;
    int r = idx >> 6, c = idx & 63;
    int tr = r + attn[0];
    int tc = c + attn[1];
    int rr = tr >> 1; if (tr & 1) rr += (rr & 1);
    int cc = tc >> 1; if (tc & 1) cc += (cc & 1);
    return rr * WD + cc;
}

// ---------------------------------------------------------------------------
// 0) init: counts = 1 (diagonal always >= 0), g_best = INT_MAX
// ---------------------------------------------------------------------------
__global__ void init_kernel() {
    int i = blockIdx.x * blockDim.x + threadIdx.x;
    if (i < NPTS) g_counts[i] = 1;
    if (i == 0) g_best = INT_MAX;
}

// ---------------------------------------------------------------------------
// 1) triangular count-GEMM, exact fp32 via packed FFMA2 (fma.rn.f32x2).
//    128x128 tile, 16x16 threads, per-thread 8x8 as 4x8 f32x2 pairs over M.
//    NO register cap (occ 1) -> no spills in the FFMA2 stream.
// ---------------------------------------------------------------------------
__global__ __launch_bounds__(256)
void count_ffma2(const float* __restrict__ X) {
    // decode triangular tile index t -> (bi, bj), bj >= bi
    int t = blockIdx.x;
    int bi = (int)((65.0 - sqrt(4225.0 - 8.0 * (double)t)) * 0.5);
    while (bi * (65 - bi) / 2 > t) bi--;
    while ((bi + 1) * (64 - bi) / 2 <= t) bi++;
    int bj = bi + (t - bi * (65 - bi) / 2);

    __shared__ __align__(16) float As[2][BK][BM + 4];
    __shared__ __align__(16) float Bs[2][BK][BM + 4];
    __shared__ int rowSum[BM];
    __shared__ int colSum[BM];

    int tid = threadIdx.x;
    int tx = tid & 15, ty = tid >> 4;
    int i0 = bi * BM, j0 = bj * BM;

    int lrow = tid >> 1;          // 0..127
    int lq4  = (tid & 1) * 8;     // 8 consecutive floats per thread

    // acc pairs over M: acc2[p][n] = {(ty*8+2p, tx*8+n), (ty*8+2p+1, tx*8+n)}
    unsigned long long acc2[4][8];
    #pragma unroll
    for (int p = 0; p < 4; p++)
        #pragma unroll
        for (int n = 0; n < 8; n++) acc2[p][n] = 0ull;

    float4 ra0, ra1, rb0, rb1;
    const float* abase = X + (size_t)(i0 + lrow) * DIM + lq4;
    const float* bbase = X + (size_t)(j0 + lrow) * DIM + lq4;

#define LDG_TILE(kt) {                                         \
        const float* ap = abase + (kt) * BK;                   \
        const float* bp = bbase + (kt) * BK;                   \
        ra0 = *(const float4*)(ap);  ra1 = *(const float4*)(ap + 4); \
        rb0 = *(const float4*)(bp);  rb1 = *(const float4*)(bp + 4); }

#define STS_TILE(buf) {                                        \
        As[buf][lq4+0][lrow]=ra0.x; As[buf][lq4+1][lrow]=ra0.y; \
        As[buf][lq4+2][lrow]=ra0.z; As[buf][lq4+3][lrow]=ra0.w; \
        As[buf][lq4+4][lrow]=ra1.x; As[buf][lq4+5][lrow]=ra1.y; \
        As[buf][lq4+6][lrow]=ra1.z; As[buf][lq4+7][lrow]=ra1.w; \
        Bs[buf][lq4+0][lrow]=rb0.x; Bs[buf][lq4+1][lrow]=rb0.y; \
        Bs[buf][lq4+2][lrow]=rb0.z; Bs[buf][lq4+3][lrow]=rb0.w; \
        Bs[buf][lq4+4][lrow]=rb1.x; Bs[buf][lq4+5][lrow]=rb1.y; \
        Bs[buf][lq4+6][lrow]=rb1.z; Bs[buf][lq4+7][lrow]=rb1.w; }

    LDG_TILE(0);
    STS_TILE(0);
    __syncthreads();

    for (int kt = 0; kt < NKT; kt++) {
        int buf = kt & 1;
        if (kt + 1 < NKT) LDG_TILE(kt + 1);

        #pragma unroll
        for (int k = 0; k < BK; k++) {
            // a: 8 consecutive rows -> 4 packed f32x2 (no movs)
            const ulonglong2* ap = (const ulonglong2*)&As[buf][k][ty * 8];
            ulonglong2 a01 = ap[0], a23 = ap[1];
            unsigned long long av[4];
            av[0] = a01.x; av[1] = a01.y; av[2] = a23.x; av[3] = a23.y;
            // b: 8 consecutive cols, duplicate each into a f32x2
            const float4* bp = (const float4*)&Bs[buf][k][tx * 8];
            float4 b0 = bp[0], b1 = bp[1];
            float bf[8] = {b0.x, b0.y, b0.z, b0.w, b1.x, b1.y, b1.z, b1.w};
            unsigned long long b2[8];
            #pragma unroll
            for (int n = 0; n < 8; n++)
                asm("mov.b64 %0, {%1, %2};" : "=l"(b2[n]) : "f"(bf[n]), "f"(bf[n]));
            #pragma unroll
            for (int p = 0; p < 4; p++)
                #pragma unroll
                for (int n = 0; n < 8; n++)
                    asm("fma.rn.f32x2 %0, %1, %2, %0;"
                        : "+l"(acc2[p][n]) : "l"(av[p]), "l"(b2[n]));
        }

        if (kt + 1 < NKT) STS_TILE(buf ^ 1);
        __syncthreads();
    }
#undef LDG_TILE
#undef STS_TILE

    // ---- epilogue: count nonnegatives per row and per column ----
    if (tid < BM) { rowSum[tid] = 0; colSum[tid] = 0; }
    __syncthreads();

    bool diag = (bi == bj);
    int rcnt[8], ccnt[8];
    #pragma unroll
    for (int m = 0; m < 8; m++) { rcnt[m] = 0; ccnt[m] = 0; }

    #pragma unroll
    for (int p = 0; p < 4; p++) {
        #pragma unroll
        for (int n = 0; n < 8; n++) {
            unsigned long long a = acc2[p][n];
            float vlo = __uint_as_float((unsigned)(a & 0xffffffffull));
            float vhi = __uint_as_float((unsigned)(a >> 32));
            int gj = j0 + tx * 8 + n;
            int gilo = i0 + ty * 8 + 2 * p;
            int clo = (vlo >= 0.0f) && (!diag || gj > gilo);
            int chi = (vhi >= 0.0f) && (!diag || gj > gilo + 1);
            rcnt[2 * p]     += clo;
            rcnt[2 * p + 1] += chi;
            ccnt[n] += clo + chi;
        }
    }
    #pragma unroll
    for (int m = 0; m < 8; m++) atomicAdd(&rowSum[ty * 8 + m], rcnt[m]);
    #pragma unroll
    for (int n = 0; n < 8; n++) atomicAdd(&colSum[tx * 8 + n], ccnt[n]);
    __syncthreads();

    if (tid < BM) {
        if (rowSum[tid]) atomicAdd(&g_counts[i0 + tid], rowSum[tid]);
        if (colSum[tid]) atomicAdd(&g_counts[j0 + tid], colSum[tid]);
    }
}

// ---------------------------------------------------------------------------
// 2) grid-wide argmin of counts via packed key atomicMin (first occurrence)
// ---------------------------------------------------------------------------
__global__ void argmin_kernel() {
    int i = blockIdx.x * blockDim.x + threadIdx.x;   // 4096 threads
    int key = g_counts[i] * 4096 + i;
    #pragma unroll
    for (int o = 16; o > 0; o >>= 1)
        key = min(key, __shfl_xor_sync(0xffffffffu, key, o));
    if ((threadIdx.x & 31) == 0) atomicMin(&g_best, key);
}

// ---------------------------------------------------------------------------
// 3) sim[seed][j] for all j + initial mask. warp per j, float4 loads.
// ---------------------------------------------------------------------------
__global__ void seedrow_kernel(const float* __restrict__ X,
                               const int* __restrict__ attn) {
    int gwarp = (blockIdx.x * blockDim.x + threadIdx.x) >> 5;
    int lane  = threadIdx.x & 31;
    if (gwarp >= NPTS) return;
    int seed = blend_seed(g_best, attn);
    const float4* xs = (const float4*)(X + (size_t)seed * DIM);
    const float4* xj = (const float4*)(X + (size_t)gwarp * DIM);
    float p = 0.0f;
    #pragma unroll
    for (int q = 0; q < 6; q++) {
        float4 u = xs[lane + 32 * q], w = xj[lane + 32 * q];
        p += u.x * w.x + u.y * w.y + u.z * w.z + u.w * w.w;
    }
    #pragma unroll
    for (int o = 16; o > 0; o >>= 1) p += __shfl_down_sync(0xffffffffu, p, o);
    if (lane == 0) {
        g_simseed[gwarp] = p;
        g_s[gwarp] = (p >= 0.0f) ? 1 : 0;
    }
}

// ---------------------------------------------------------------------------
// 4) top-100 via bitonic sort on packed 64-bit keys:
//    key = (orderable(value) << 32) | (NPTS-1-i)  -> desc sort == desc value,
//    ties asc index. Then mask s to kept set.
// ---------------------------------------------------------------------------
__device__ __forceinline__ unsigned ford(float v) {   // monotonic float->uint
    unsigned u = __float_as_uint(v);
    return (u & 0x80000000u) ? ~u : (u | 0x80000000u);
}
__global__ void topk_kernel(const int* __restrict__ attn) {
    __shared__ unsigned long long sk[NPTS];
    int tid = threadIdx.x;   // 1024 threads
    int seed = blend_seed(g_best, attn);
    for (int i = tid; i < NPTS; i += 1024)
        sk[i] = ((unsigned long long)ford(g_simseed[i]) << 32)
              | (unsigned)(NPTS - 1 - i);
    __syncthreads();
    for (int k = 2; k <= NPTS; k <<= 1) {
        for (int j = k >> 1; j > 0; j >>= 1) {
            for (int i = tid; i < NPTS; i += 1024) {
                int ixj = i ^ j;
                if (ixj > i) {
                    unsigned long long k1 = sk[i], k2 = sk[ixj];
                    bool g = (k1 < k2);                 // k1 later in DESC order
                    bool dirDesc = ((i & k) == 0);
                    if (g == dirDesc) { sk[i] = k2; sk[ixj] = k1; }
                }
            }
            __syncthreads();
        }
    }
    unsigned long long k99 = sk[KTOP - 1];
    for (int i = tid; i < NPTS; i += 1024) {
        int s = g_s[i];
        if (i == seed) s = 1;
        unsigned long long ki = ((unsigned long long)ford(g_simseed[i]) << 32)
                              | (unsigned)(NPTS - 1 - i);
        g_s[i] = (ki >= k99) ? s : 0;
    }
}

// ---------------------------------------------------------------------------
// 5) sequential expansion, single warp, float4 loads, register accumulator.
// ---------------------------------------------------------------------------
__global__ void scan_kernel(const float* __restrict__ X) {
    __shared__ int list[KTOP + 32];
    int lane = threadIdx.x;   // 32 threads

    int cnt = 0;
    for (int c = 0; c < NPTS / 32; c++) {
        int idx = c * 32 + lane;
        int val = g_s[idx];
        unsigned m = __ballot_sync(0xffffffffu, val != 0);
        if (val) {
            int pos = cnt + __popc(m & ((1u << lane) - 1));
            if (pos < KTOP + 32) list[pos] = idx;
        }
        cnt += __popc(m);
    }
    int na = (cnt < KTOP + 32) ? cnt : (KTOP + 32);
    __syncwarp();

    float4 v4[6];
    #pragma unroll
    for (int q = 0; q < 6; q++) v4[q] = make_float4(0.f, 0.f, 0.f, 0.f);
    for (int l = 0; l < na; l++) {
        const float4* x = (const float4*)(X + (size_t)list[l] * DIM);
        #pragma unroll
        for (int q = 0; q < 6; q++) {
            float4 u = x[lane + 32 * q];
            v4[q].x += u.x; v4[q].y += u.y; v4[q].z += u.z; v4[q].w += u.w;
        }
    }

    for (int l = 0; l < na; l++) {
        int i = list[l];
        const float4* x = (const float4*)(X + (size_t)i * DIM);
        float4 xr[6];
        float dot = 0.0f;
        #pragma unroll
        for (int q = 0; q < 6; q++) {
            xr[q] = x[lane + 32 * q];
            dot += xr[q].x * v4[q].x + xr[q].y * v4[q].y
                 + xr[q].z * v4[q].z + xr[q].w * v4[q].w;
        }
        #pragma unroll
        for (int o = 16; o > 0; o >>= 1) dot += __shfl_xor_sync(0xffffffffu, dot, o);
        if (dot <= 0.0f) {                 // grows = (sum > 0) fails -> drop
            if (lane == 0) g_s[i] = 0;
            #pragma unroll
            for (int q = 0; q < 6; q++) {
                v4[q].x -= xr[q].x; v4[q].y -= xr[q].y;
                v4[q].z -= xr[q].z; v4[q].w -= xr[q].w;
            }
        }
    }
}

// ---------------------------------------------------------------------------
// 6) 8-connected components: in-place min-label propagation to fixpoint.
// ---------------------------------------------------------------------------
__global__ void cc_kernel(float* __restrict__ outp) {
    __shared__ int lab[66 * 66];
    __shared__ int changed;
    const int BIG = NPTS + 1;
    int tid = threadIdx.x;   // 1024 threads

    for (int p = tid; p < 66 * 66; p += 1024) lab[p] = BIG;
    __syncthreads();

    int fgp[4], pos[4];
    #pragma unroll
    for (int q = 0; q < 4; q++) {
        int p = tid + q * 1024;
        int r = p >> 6, c = p & 63;
        pos[q] = (r + 1) * 66 + (c + 1);
        fgp[q] = g_s[p];
        lab[pos[q]] = fgp[q] ? (p + 1) : BIG;
    }
    __syncthreads();

    while (true) {
        if (tid == 0) changed = 0;
        __syncthreads();
        int lc = 0;
        #pragma unroll
        for (int q = 0; q < 4; q++) {
            if (fgp[q]) {
                int pp = pos[q];
                int m = lab[pp];
                m = min(m, lab[pp - 67]); m = min(m, lab[pp - 66]); m = min(m, lab[pp - 65]);
                m = min(m, lab[pp - 1]);                            m = min(m, lab[pp + 1]);
                m = min(m, lab[pp + 65]); m = min(m, lab[pp + 66]); m = min(m, lab[pp + 67]);
                if (m < lab[pp]) { lab[pp] = m; lc = 1; }
            }
        }
        if (lc) changed = 1;
        __syncthreads();
        int done = !changed;
        __syncthreads();
        if (done) break;
    }

    #pragma unroll
    for (int q = 0; q < 4; q++) {
        int p = tid + q * 1024;
        outp[p] = fgp[q] ? (float)lab[pos[q]] : 0.0f;
    }
}

// ---------------------------------------------------------------------------
extern "C" void kernel_launch(void* const* d_in, const int* in_sizes, int n_in,
                              void* d_out, int out_size) {
    const float* X;
    const int*   attn;
    if (n_in >= 2 && in_sizes[0] == 2) {
        attn = (const int*)d_in[0];
        X    = (const float*)d_in[1];
    } else {
        X    = (const float*)d_in[0];
        attn = (const int*)d_in[1];
    }
    float* outp = (float*)d_out;

    init_kernel<<<16, 256>>>();
    count_ffma2<<<528, 256>>>(X);
    argmin_kernel<<<16, 256>>>();
    seedrow_kernel<<<NPTS / 8, 256>>>(X, attn);
    topk_kernel<<<1, 1024>>>(attn);
    scan_kernel<<<1, 32>>>(X);
    cc_kernel<<<1, 1024>>>(outp);
}